// round 7
// baseline (speedup 1.0000x reference)
#include <cuda_runtime.h>
#include <math_constants.h>
#include <cstdint>

#define NQ   4096
#define NK   4096
#define FDIM 256
#define RADIUS2 9.0f
#define MAXN 128
#define QPC  8
#define NCELL 512          // query sort: 8^3 cells of 2.0
#define KCD  5             // key grid: 5^3 cells of 3.2
#define KINV 0.3125f

__device__ float g_q[NQ * FDIM];
__device__ float g_k[NK * FDIM];      // K rows in SORTED key order
__device__ float g_v[NK * FDIM];      // V rows in SORTED key order
__device__ float g_att[NQ * FDIM];
__device__ int   g_sorted[NQ];
__device__ int   g_kidx[NK];          // sorted pos -> original key index
__device__ int   g_kstart[KCD*KCD*KCD + 1];
__device__ float g_ck2[NK * 3];       // key coords in sorted order

// ======================= 3xTF32 mma.sync GEMM =======================
__device__ __forceinline__ void split_tf32(float x, uint32_t& hi, uint32_t& lo) {
    uint32_t h;
    asm("cvt.rna.tf32.f32 %0, %1;" : "=r"(h) : "f"(x));
    float r = x - __uint_as_float(h);
    uint32_t l;
    asm("cvt.rna.tf32.f32 %0, %1;" : "=r"(l) : "f"(r));
    hi = h; lo = l;
}

__device__ __forceinline__ void mma_tf32(float* d, const uint32_t* a, const uint32_t* b) {
    asm volatile(
        "mma.sync.aligned.m16n8k8.row.col.f32.tf32.tf32.f32 "
        "{%0,%1,%2,%3}, {%4,%5,%6,%7}, {%8,%9}, {%0,%1,%2,%3};"
        : "+f"(d[0]), "+f"(d[1]), "+f"(d[2]), "+f"(d[3])
        : "r"(a[0]), "r"(a[1]), "r"(a[2]), "r"(a[3]), "r"(b[0]), "r"(b[1]));
}

// C[BM x 64] tile of C = A[perm] @ W^T + b.  perm==null -> identity.
template<int MFRAGS>
__device__ __forceinline__ void gemm_tc_body(const float* __restrict__ A,
                                             const float* __restrict__ W,
                                             const float* __restrict__ b,
                                             float* __restrict__ C,
                                             const int* __restrict__ perm)
{
    constexpr int BM = 64 * MFRAGS;
    __shared__ float As[BM][36];
    __shared__ float Ws[64][36];

    const int tid   = threadIdx.x;
    const int wid   = tid >> 5;
    const int lane  = tid & 31;
    const int warpM = wid >> 1;
    const int warpN = wid & 1;
    const int m0 = blockIdx.x * BM;
    const int n0 = blockIdx.y * 64;

    const int qrow = lane >> 2;
    const int qk   = lane & 3;

    float acc[MFRAGS][4][4] = {};

    for (int kt = 0; kt < 256; kt += 32) {
        #pragma unroll
        for (int i = 0; i < BM / 32; i++) {
            int f = tid + i * 256;
            int row = f >> 3, kq = (f & 7) * 4;
            int grow = perm ? perm[m0 + row] : (m0 + row);
            float4 v = *(const float4*)(A + (size_t)grow * 256 + kt + kq);
            As[row][kq + 0] = v.x; As[row][kq + 1] = v.y;
            As[row][kq + 2] = v.z; As[row][kq + 3] = v.w;
        }
        #pragma unroll
        for (int i = 0; i < 2; i++) {
            int f = tid + i * 256;
            int row = f >> 3, kq = (f & 7) * 4;
            float4 v = *(const float4*)(W + (size_t)(n0 + row) * 256 + kt + kq);
            Ws[row][kq + 0] = v.x; Ws[row][kq + 1] = v.y;
            Ws[row][kq + 2] = v.z; Ws[row][kq + 3] = v.w;
        }
        __syncthreads();

        #pragma unroll
        for (int ks = 0; ks < 4; ks++) {
            const int k0 = ks * 8;
            uint32_t ah[MFRAGS][4], al[MFRAGS][4];
            #pragma unroll
            for (int mf = 0; mf < MFRAGS; mf++) {
                int r = warpM * (16 * MFRAGS) + mf * 16 + qrow;
                split_tf32(As[r][k0 + qk],          ah[mf][0], al[mf][0]);
                split_tf32(As[r + 8][k0 + qk],      ah[mf][1], al[mf][1]);
                split_tf32(As[r][k0 + qk + 4],      ah[mf][2], al[mf][2]);
                split_tf32(As[r + 8][k0 + qk + 4],  ah[mf][3], al[mf][3]);
            }
            #pragma unroll
            for (int nf = 0; nf < 4; nf++) {
                int cn = warpN * 32 + nf * 8 + qrow;
                uint32_t bh[2], bl[2];
                split_tf32(Ws[cn][k0 + qk],     bh[0], bl[0]);
                split_tf32(Ws[cn][k0 + qk + 4], bh[1], bl[1]);
                #pragma unroll
                for (int mf = 0; mf < MFRAGS; mf++) {
                    mma_tf32(acc[mf][nf], ah[mf], bh);
                    mma_tf32(acc[mf][nf], ah[mf], bl);
                    mma_tf32(acc[mf][nf], al[mf], bh);
                }
            }
        }
        __syncthreads();
    }

    #pragma unroll
    for (int mf = 0; mf < MFRAGS; mf++) {
        int r0 = m0 + warpM * (16 * MFRAGS) + mf * 16 + qrow;
        #pragma unroll
        for (int nf = 0; nf < 4; nf++) {
            int c0 = n0 + warpN * 32 + nf * 8 + qk * 2;
            float b0 = b[c0], b1 = b[c0 + 1];
            *(float2*)(C + (size_t)r0 * 256 + c0) =
                make_float2(acc[mf][nf][0] + b0, acc[mf][nf][1] + b1);
            *(float2*)(C + (size_t)(r0 + 8) * 256 + c0) =
                make_float2(acc[mf][nf][2] + b0, acc[mf][nf][3] + b1);
        }
    }
}

__global__ void __launch_bounds__(256)
gemm_qkv_tc(const float* __restrict__ curf, const float* __restrict__ histf,
            const float* __restrict__ Wq, const float* __restrict__ bq, float* __restrict__ Cq,
            const float* __restrict__ Wk, const float* __restrict__ bk, float* __restrict__ Ck,
            const float* __restrict__ Wv, const float* __restrict__ bv, float* __restrict__ Cv,
            const int* __restrict__ kidx)
{
    const float *A, *W, *b; float *C; const int* perm;
    if (blockIdx.z == 0)      { A = curf;  W = Wq; b = bq; C = Cq; perm = nullptr; }
    else if (blockIdx.z == 1) { A = histf; W = Wk; b = bk; C = Ck; perm = kidx; }
    else                      { A = histf; W = Wv; b = bv; C = Cv; perm = kidx; }
    gemm_tc_body<2>(A, W, b, C, perm);
}

__global__ void __launch_bounds__(256)
gemm_o_tc(const float* __restrict__ A, const float* __restrict__ W,
          const float* __restrict__ b, float* __restrict__ C)
{
    gemm_tc_body<1>(A, W, b, C, nullptr);
}

// ======================= query spatial sort (unchanged) =======================
__global__ void __launch_bounds__(512)
sort_kernel(const float* __restrict__ cq)
{
    __shared__ int  scnt[NCELL];
    __shared__ int  soff[NCELL];
    __shared__ short qcell[NQ];
    __shared__ int  wsum[16];

    const int t = threadIdx.x;
    scnt[t] = 0;
    __syncthreads();

    for (int q = t; q < NQ; q += 512) {
        int cx = (int)(cq[3 * q + 0] * 0.5f); cx = cx < 0 ? 0 : (cx > 7 ? 7 : cx);
        int cy = (int)(cq[3 * q + 1] * 0.5f); cy = cy < 0 ? 0 : (cy > 7 ? 7 : cy);
        int cz = (int)(cq[3 * q + 2] * 0.5f); cz = cz < 0 ? 0 : (cz > 7 ? 7 : cz);
        int m = 0;
        #pragma unroll
        for (int bbit = 0; bbit < 3; bbit++) {
            m |= ((cx >> bbit) & 1) << (3 * bbit + 2);
            m |= ((cy >> bbit) & 1) << (3 * bbit + 1);
            m |= ((cz >> bbit) & 1) << (3 * bbit + 0);
        }
        qcell[q] = (short)m;
        atomicAdd(&scnt[m], 1);
    }
    __syncthreads();

    {
        const int lane = t & 31, w = t >> 5;
        int v = scnt[t];
        int x = v;
        #pragma unroll
        for (int off = 1; off < 32; off <<= 1) {
            int y = __shfl_up_sync(0xffffffffu, x, off);
            if (lane >= off) x += y;
        }
        if (lane == 31) wsum[w] = x;
        __syncthreads();
        if (t < 16) {
            int s = wsum[t];
            int xs = s;
            #pragma unroll
            for (int off = 1; off < 16; off <<= 1) {
                int y = __shfl_up_sync(0xffffu, xs, off);
                if (t >= off) xs += y;
            }
            wsum[t] = xs - s;
        }
        __syncthreads();
        soff[t] = wsum[w] + x - v;
    }
    __syncthreads();

    scnt[t] = 0;
    __syncthreads();

    for (int q = t; q < NQ; q += 512) {
        int cell = qcell[q];
        int pos = atomicAdd(&scnt[cell], 1);
        g_sorted[soff[cell] + pos] = q;
    }
}

// ======================= key cell-grid sort =======================
__global__ void __launch_bounds__(512)
sort_k_kernel(const float* __restrict__ ck)
{
    __shared__ int  scnt[128];
    __shared__ int  soff[128];
    __shared__ short kcell[NK];
    __shared__ int  wsum[4];

    const int t = threadIdx.x;
    if (t < 128) scnt[t] = 0;
    __syncthreads();

    for (int j = t; j < NK; j += 512) {
        float x = ck[3 * j + 0], y = ck[3 * j + 1], z = ck[3 * j + 2];
        int cx = (int)(x * KINV); cx = cx < 0 ? 0 : (cx > KCD - 1 ? KCD - 1 : cx);
        int cy = (int)(y * KINV); cy = cy < 0 ? 0 : (cy > KCD - 1 ? KCD - 1 : cy);
        int cz = (int)(z * KINV); cz = cz < 0 ? 0 : (cz > KCD - 1 ? KCD - 1 : cz);
        int c = (cx * KCD + cy) * KCD + cz;
        kcell[j] = (short)c;
        atomicAdd(&scnt[c], 1);
    }
    __syncthreads();

    if (t < 128) {
        const int lane = t & 31, w = t >> 5;
        int v = scnt[t];
        int x = v;
        #pragma unroll
        for (int off = 1; off < 32; off <<= 1) {
            int y = __shfl_up_sync(0xffffffffu, x, off);
            if (lane >= off) x += y;
        }
        if (lane == 31) wsum[w] = x;
        __syncwarp();
        soff[t] = x - v;     // intra-warp exclusive
    }
    __syncthreads();
    if (t < 128) {
        const int w = t >> 5;
        int base = 0;
        for (int i = 0; i < w; i++) base += wsum[i];
        soff[t] += base;
        if (t <= KCD * KCD * KCD) g_kstart[t] = soff[t] + ((t == 127) ? 0 : 0);
    }
    __syncthreads();
    // g_kstart[c] for c in [0,125]; cells 125..127 empty so soff[125] == NK
    if (t == 0) g_kstart[KCD * KCD * KCD] = NK;
    __syncthreads();

    if (t < 128) scnt[t] = 0;
    __syncthreads();

    for (int j = t; j < NK; j += 512) {
        int c = kcell[j];
        int p = atomicAdd(&scnt[c], 1);
        int pos = soff[c] + p;
        g_kidx[pos] = j;
        g_ck2[3 * pos + 0] = ck[3 * j + 0];
        g_ck2[3 * pos + 1] = ck[3 * j + 1];
        g_ck2[3 * pos + 2] = ck[3 * j + 2];
    }
}

// ======================= sparse attention w/ key grid =======================
__global__ void __launch_bounds__(256)
attn_kernel(const float* __restrict__ cq,
            const int* __restrict__ sorted,
            float* __restrict__ out)
{
    const int tid  = threadIdx.x;
    const int warp = tid >> 5;
    const int lane = tid & 31;

    __shared__ int nbr[8][MAXN];
    __shared__ int cnt[8];
    __shared__ int offs[9];
    __shared__ int list[8 * MAXN];
    __shared__ int kst[KCD * KCD * KCD + 1];

    for (int i = tid; i < KCD * KCD * KCD + 1; i += 256) kst[i] = g_kstart[i];

    const int head = warp;
    const int sub  = lane >> 3;
    const int dq   = (lane & 7) * 4;
    const float* kb = g_k + head * 32 + dq;
    const float* vb = g_v + head * 32 + dq;
    __syncthreads();

    for (int qq = 0; qq < QPC; qq++) {
        const int qi = sorted[blockIdx.x * QPC + qq];

        const float qx = cq[3 * qi + 0];
        const float qy = cq[3 * qi + 1];
        const float qz = cq[3 * qi + 2];

        int qcx = (int)(qx * KINV); qcx = qcx < 0 ? 0 : (qcx > KCD - 1 ? KCD - 1 : qcx);
        int qcy = (int)(qy * KINV); qcy = qcy < 0 ? 0 : (qcy > KCD - 1 ? KCD - 1 : qcy);
        int qcz = (int)(qz * KINV); qcz = qcz < 0 ? 0 : (qcz > KCD - 1 ? KCD - 1 : qcz);

        // Phase 1: scan the 27 neighbor cells, split across 8 warps.
        int c = 0;
        for (int ci = warp; ci < 27; ci += 8) {
            int cx = qcx + (ci % 3) - 1;
            int cy = qcy + ((ci / 3) % 3) - 1;
            int cz = qcz + (ci / 9) - 1;
            if (cx < 0 || cx >= KCD || cy < 0 || cy >= KCD || cz < 0 || cz >= KCD)
                continue;
            int cell = (cx * KCD + cy) * KCD + cz;
            int s = kst[cell], e = kst[cell + 1];
            for (int bse = s; bse < e; bse += 32) {
                int j = bse + lane;
                bool pass = false;
                if (j < e) {
                    float dx = qx - g_ck2[3 * j + 0];
                    float dy = qy - g_ck2[3 * j + 1];
                    float dz = qz - g_ck2[3 * j + 2];
                    pass = (dx * dx + dy * dy + dz * dz) <= RADIUS2;
                }
                unsigned mk = __ballot_sync(0xffffffffu, pass);
                if (pass) {
                    int pos = c + __popc(mk & ((1u << lane) - 1u));
                    if (pos < MAXN) nbr[warp][pos] = j;
                }
                c += __popc(mk);
            }
        }
        if (lane == 0) cnt[warp] = (c < MAXN) ? c : MAXN;
        __syncthreads();

        if (tid == 0) {
            int o = 0;
            #pragma unroll
            for (int w = 0; w < 8; w++) { offs[w] = o; o += cnt[w]; }
            offs[8] = o;
        }
        __syncthreads();

        {
            const int n = cnt[warp], o = offs[warp];
            for (int i = lane; i < n; i += 32) list[o + i] = nbr[warp][i];
        }
        __syncthreads();

        // Phase 2: no-max softmax; 8 lanes/neighbor, 4 neighbors/pass
        const int ntot = offs[8];
        const float4 qv = *(const float4*)(g_q + qi * 256 + head * 32 + dq);

        float l = 0.0f;
        float4 acc = make_float4(0.f, 0.f, 0.f, 0.f);

        #pragma unroll 2
        for (int base = 0; base < ntot; base += 4) {
            const int nb = ntot - base;
            int g = sub;
            if (g > nb - 1) g = nb - 1;
            const int j = list[base + g];

            const float4 kv = *(const float4*)(kb + j * 256);
            float p = qv.x * kv.x;
            p = fmaf(qv.y, kv.y, p);
            p = fmaf(qv.z, kv.z, p);
            p = fmaf(qv.w, kv.w, p);
            p += __shfl_xor_sync(0xffffffffu, p, 1);
            p += __shfl_xor_sync(0xffffffffu, p, 2);
            p += __shfl_xor_sync(0xffffffffu, p, 4);

            float e = __expf(p * 0.17677669529663687f);
            if (sub > nb - 1) e = 0.0f;

            l += e;
            const float4 vv = *(const float4*)(vb + j * 256);
            acc.x = fmaf(e, vv.x, acc.x);
            acc.y = fmaf(e, vv.y, acc.y);
            acc.z = fmaf(e, vv.z, acc.z);
            acc.w = fmaf(e, vv.w, acc.w);
        }

        #pragma unroll
        for (int off = 8; off <= 16; off <<= 1) {
            acc.x += __shfl_xor_sync(0xffffffffu, acc.x, off);
            acc.y += __shfl_xor_sync(0xffffffffu, acc.y, off);
            acc.z += __shfl_xor_sync(0xffffffffu, acc.z, off);
            acc.w += __shfl_xor_sync(0xffffffffu, acc.w, off);
            l     += __shfl_xor_sync(0xffffffffu, l, off);
        }

        if (sub == 0) {
            float inv = 1.0f / l;
            float4 o = make_float4(acc.x * inv, acc.y * inv, acc.z * inv, acc.w * inv);
            *(float4*)(out + qi * 256 + head * 32 + dq) = o;
        }
        __syncthreads();
    }
}

// ---------------------------------------------------------------------------
extern "C" void kernel_launch(void* const* d_in, const int* in_sizes, int n_in,
                              void* d_out, int out_size)
{
    const float* cur_f  = (const float*)d_in[0];
    const float* hist_f = (const float*)d_in[1];
    const float* cur_c  = (const float*)d_in[2];
    const float* hist_c = (const float*)d_in[3];
    const float* Wq = (const float*)d_in[4];
    const float* bq = (const float*)d_in[5];
    const float* Wk = (const float*)d_in[6];
    const float* bk = (const float*)d_in[7];
    const float* Wv = (const float*)d_in[8];
    const float* bv = (const float*)d_in[9];
    const float* Wo = (const float*)d_in[10];
    const float* bo = (const float*)d_in[11];
    float* out = (float*)d_out;

    float *pq, *pk, *pv, *patt;
    int *psorted, *pkidx;
    cudaGetSymbolAddress((void**)&pq,   g_q);
    cudaGetSymbolAddress((void**)&pk,   g_k);
    cudaGetSymbolAddress((void**)&pv,   g_v);
    cudaGetSymbolAddress((void**)&patt, g_att);
    cudaGetSymbolAddress((void**)&psorted, g_sorted);
    cudaGetSymbolAddress((void**)&pkidx, g_kidx);

    sort_kernel<<<1, 512>>>(cur_c);
    sort_k_kernel<<<1, 512>>>(hist_c);

    dim3 gqkv(NQ / 128, FDIM / 64, 3);
    gemm_qkv_tc<<<gqkv, 256>>>(cur_f, hist_f,
                               Wq, bq, pq,
                               Wk, bk, pk,
                               Wv, bv, pv,
                               pkidx);

    attn_kernel<<<NQ / QPC, 256>>>(cur_c, psorted, patt);

    dim3 go(NQ / 64, FDIM / 64);
    gemm_o_tc<<<go, 256>>>(patt, Wo, bo, out);
}

// round 13
// speedup vs baseline: 1.1802x; 1.1802x over previous
#include <cuda_runtime.h>
#include <math_constants.h>
#include <cstdint>

#define NQ   4096
#define NK   4096
#define FDIM 256
#define RADIUS2 9.0f
#define MAXN 192           // per-query neighbor cap (mean 113, sd ~10.5)
#define NCELL 512          // query sort: 8^3 cells of 2.0
#define KCD  5             // key grid: 5^3 cells of 3.2
#define KINV 0.3125f
#define QPW  4             // queries per CTA (1 per warp)

__device__ float g_q[NQ * FDIM];
__device__ float g_k[NK * FDIM];      // K rows in SORTED key order
__device__ float g_v[NK * FDIM];      // V rows in SORTED key order
__device__ float g_att[NQ * FDIM];
__device__ int   g_sorted[NQ];
__device__ int   g_kidx[NK];
__device__ int   g_kstart[KCD*KCD*KCD + 1];
__device__ float g_ck2[NK * 3];       // key coords in sorted order

// ======================= 3xTF32 mma.sync GEMM =======================
__device__ __forceinline__ void split_tf32(float x, uint32_t& hi, uint32_t& lo) {
    uint32_t h;
    asm("cvt.rna.tf32.f32 %0, %1;" : "=r"(h) : "f"(x));
    float r = x - __uint_as_float(h);
    uint32_t l;
    asm("cvt.rna.tf32.f32 %0, %1;" : "=r"(l) : "f"(r));
    hi = h; lo = l;
}

__device__ __forceinline__ void mma_tf32(float* d, const uint32_t* a, const uint32_t* b) {
    asm volatile(
        "mma.sync.aligned.m16n8k8.row.col.f32.tf32.tf32.f32 "
        "{%0,%1,%2,%3}, {%4,%5,%6,%7}, {%8,%9}, {%0,%1,%2,%3};"
        : "+f"(d[0]), "+f"(d[1]), "+f"(d[2]), "+f"(d[3])
        : "r"(a[0]), "r"(a[1]), "r"(a[2]), "r"(a[3]), "r"(b[0]), "r"(b[1]));
}

template<int MFRAGS>
__device__ __forceinline__ void gemm_tc_body(const float* __restrict__ A,
                                             const float* __restrict__ W,
                                             const float* __restrict__ b,
                                             float* __restrict__ C,
                                             const int* __restrict__ perm)
{
    constexpr int BM = 64 * MFRAGS;
    __shared__ float As[BM][36];
    __shared__ float Ws[64][36];

    const int tid   = threadIdx.x;
    const int wid   = tid >> 5;
    const int lane  = tid & 31;
    const int warpM = wid >> 1;
    const int warpN = wid & 1;
    const int m0 = blockIdx.x * BM;
    const int n0 = blockIdx.y * 64;

    const int qrow = lane >> 2;
    const int qk   = lane & 3;

    float acc[MFRAGS][4][4] = {};

    for (int kt = 0; kt < 256; kt += 32) {
        #pragma unroll
        for (int i = 0; i < BM / 32; i++) {
            int f = tid + i * 256;
            int row = f >> 3, kq = (f & 7) * 4;
            int grow = perm ? perm[m0 + row] : (m0 + row);
            float4 v = *(const float4*)(A + (size_t)grow * 256 + kt + kq);
            As[row][kq + 0] = v.x; As[row][kq + 1] = v.y;
            As[row][kq + 2] = v.z; As[row][kq + 3] = v.w;
        }
        #pragma unroll
        for (int i = 0; i < 2; i++) {
            int f = tid + i * 256;
            int row = f >> 3, kq = (f & 7) * 4;
            float4 v = *(const float4*)(W + (size_t)(n0 + row) * 256 + kt + kq);
            Ws[row][kq + 0] = v.x; Ws[row][kq + 1] = v.y;
            Ws[row][kq + 2] = v.z; Ws[row][kq + 3] = v.w;
        }
        __syncthreads();

        #pragma unroll
        for (int ks = 0; ks < 4; ks++) {
            const int k0 = ks * 8;
            uint32_t ah[MFRAGS][4], al[MFRAGS][4];
            #pragma unroll
            for (int mf = 0; mf < MFRAGS; mf++) {
                int r = warpM * (16 * MFRAGS) + mf * 16 + qrow;
                split_tf32(As[r][k0 + qk],          ah[mf][0], al[mf][0]);
                split_tf32(As[r + 8][k0 + qk],      ah[mf][1], al[mf][1]);
                split_tf32(As[r][k0 + qk + 4],      ah[mf][2], al[mf][2]);
                split_tf32(As[r + 8][k0 + qk + 4],  ah[mf][3], al[mf][3]);
            }
            #pragma unroll
            for (int nf = 0; nf < 4; nf++) {
                int cn = warpN * 32 + nf * 8 + qrow;
                uint32_t bh[2], bl[2];
                split_tf32(Ws[cn][k0 + qk],     bh[0], bl[0]);
                split_tf32(Ws[cn][k0 + qk + 4], bh[1], bl[1]);
                #pragma unroll
                for (int mf = 0; mf < MFRAGS; mf++) {
                    mma_tf32(acc[mf][nf], ah[mf], bh);
                    mma_tf32(acc[mf][nf], ah[mf], bl);
                    mma_tf32(acc[mf][nf], al[mf], bh);
                }
            }
        }
        __syncthreads();
    }

    #pragma unroll
    for (int mf = 0; mf < MFRAGS; mf++) {
        int r0 = m0 + warpM * (16 * MFRAGS) + mf * 16 + qrow;
        #pragma unroll
        for (int nf = 0; nf < 4; nf++) {
            int c0 = n0 + warpN * 32 + nf * 8 + qk * 2;
            float b0 = b[c0], b1 = b[c0 + 1];
            *(float2*)(C + (size_t)r0 * 256 + c0) =
                make_float2(acc[mf][nf][0] + b0, acc[mf][nf][1] + b1);
            *(float2*)(C + (size_t)(r0 + 8) * 256 + c0) =
                make_float2(acc[mf][nf][2] + b0, acc[mf][nf][3] + b1);
        }
    }
}

__global__ void __launch_bounds__(256)
gemm_qkv_tc(const float* __restrict__ curf, const float* __restrict__ histf,
            const float* __restrict__ Wq, const float* __restrict__ bq, float* __restrict__ Cq,
            const float* __restrict__ Wk, const float* __restrict__ bk, float* __restrict__ Ck,
            const float* __restrict__ Wv, const float* __restrict__ bv, float* __restrict__ Cv,
            const int* __restrict__ kidx)
{
    const float *A, *W, *b; float *C; const int* perm;
    if (blockIdx.z == 0)      { A = curf;  W = Wq; b = bq; C = Cq; perm = nullptr; }
    else if (blockIdx.z == 1) { A = histf; W = Wk; b = bk; C = Ck; perm = kidx; }
    else                      { A = histf; W = Wv; b = bv; C = Cv; perm = kidx; }
    gemm_tc_body<2>(A, W, b, C, perm);
}

__global__ void __launch_bounds__(256)
gemm_o_tc(const float* __restrict__ A, const float* __restrict__ W,
          const float* __restrict__ b, float* __restrict__ C)
{
    gemm_tc_body<1>(A, W, b, C, nullptr);
}

// ======================= query spatial sort =======================
__global__ void __launch_bounds__(512)
sort_kernel(const float* __restrict__ cq)
{
    __shared__ int  scnt[NCELL];
    __shared__ int  soff[NCELL];
    __shared__ short qcell[NQ];
    __shared__ int  wsum[16];

    const int t = threadIdx.x;
    scnt[t] = 0;
    __syncthreads();

    for (int q = t; q < NQ; q += 512) {
        int cx = (int)(cq[3 * q + 0] * 0.5f); cx = cx < 0 ? 0 : (cx > 7 ? 7 : cx);
        int cy = (int)(cq[3 * q + 1] * 0.5f); cy = cy < 0 ? 0 : (cy > 7 ? 7 : cy);
        int cz = (int)(cq[3 * q + 2] * 0.5f); cz = cz < 0 ? 0 : (cz > 7 ? 7 : cz);
        int m = 0;
        #pragma unroll
        for (int bbit = 0; bbit < 3; bbit++) {
            m |= ((cx >> bbit) & 1) << (3 * bbit + 2);
            m |= ((cy >> bbit) & 1) << (3 * bbit + 1);
            m |= ((cz >> bbit) & 1) << (3 * bbit + 0);
        }
        qcell[q] = (short)m;
        atomicAdd(&scnt[m], 1);
    }
    __syncthreads();

    {
        const int lane = t & 31, w = t >> 5;
        int v = scnt[t];
        int x = v;
        #pragma unroll
        for (int off = 1; off < 32; off <<= 1) {
            int y = __shfl_up_sync(0xffffffffu, x, off);
            if (lane >= off) x += y;
        }
        if (lane == 31) wsum[w] = x;
        __syncthreads();
        if (t < 16) {
            int s = wsum[t];
            int xs = s;
            #pragma unroll
            for (int off = 1; off < 16; off <<= 1) {
                int y = __shfl_up_sync(0xffffu, xs, off);
                if (t >= off) xs += y;
            }
            wsum[t] = xs - s;
        }
        __syncthreads();
        soff[t] = wsum[w] + x - v;
    }
    __syncthreads();

    scnt[t] = 0;
    __syncthreads();

    for (int q = t; q < NQ; q += 512) {
        int cell = qcell[q];
        int pos = atomicAdd(&scnt[cell], 1);
        g_sorted[soff[cell] + pos] = q;
    }
}

// ======================= key cell-grid sort =======================
__global__ void __launch_bounds__(512)
sort_k_kernel(const float* __restrict__ ck)
{
    __shared__ int  scnt[128];
    __shared__ int  soff[128];
    __shared__ short kcell[NK];
    __shared__ int  wsum[4];

    const int t = threadIdx.x;
    if (t < 128) scnt[t] = 0;
    __syncthreads();

    for (int j = t; j < NK; j += 512) {
        float x = ck[3 * j + 0], y = ck[3 * j + 1], z = ck[3 * j + 2];
        int cx = (int)(x * KINV); cx = cx < 0 ? 0 : (cx > KCD - 1 ? KCD - 1 : cx);
        int cy = (int)(y * KINV); cy = cy < 0 ? 0 : (cy > KCD - 1 ? KCD - 1 : cy);
        int cz = (int)(z * KINV); cz = cz < 0 ? 0 : (cz > KCD - 1 ? KCD - 1 : cz);
        int c = (cx * KCD + cy) * KCD + cz;
        kcell[j] = (short)c;
        atomicAdd(&scnt[c], 1);
    }
    __syncthreads();

    if (t < 128) {
        const int lane = t & 31, w = t >> 5;
        int v = scnt[t];
        int x = v;
        #pragma unroll
        for (int off = 1; off < 32; off <<= 1) {
            int y = __shfl_up_sync(0xffffffffu, x, off);
            if (lane >= off) x += y;
        }
        if (lane == 31) wsum[w] = x;
        __syncwarp();
        soff[t] = x - v;
    }
    __syncthreads();
    if (t < 128) {
        const int w = t >> 5;
        int base = 0;
        for (int i = 0; i < w; i++) base += wsum[i];
        soff[t] += base;
        if (t <= KCD * KCD * KCD) g_kstart[t] = soff[t];
    }
    __syncthreads();
    if (t == 0) g_kstart[KCD * KCD * KCD] = NK;
    __syncthreads();

    if (t < 128) scnt[t] = 0;
    __syncthreads();

    for (int j = t; j < NK; j += 512) {
        int c = kcell[j];
        int p = atomicAdd(&scnt[c], 1);
        int pos = soff[c] + p;
        g_kidx[pos] = j;
        g_ck2[3 * pos + 0] = ck[3 * j + 0];
        g_ck2[3 * pos + 1] = ck[3 * j + 1];
        g_ck2[3 * pos + 2] = ck[3 * j + 2];
    }
}

// ======================= sparse attention: warp = query =======================
// Lane L owns dims [8L, 8L+8) -> head = L>>2 (4-lane groups). All 8 heads
// processed in one pass per neighbor. No __syncthreads in the main loops.
__global__ void __launch_bounds__(128)
attn_kernel(const float* __restrict__ cq,
            const int* __restrict__ sorted,
            float* __restrict__ out)
{
    const int tid  = threadIdx.x;
    const int warp = tid >> 5;
    const int lane = tid & 31;

    __shared__ int list_s[QPW][MAXN];
    __shared__ int kst[KCD * KCD * KCD + 1];

    for (int i = tid; i < KCD * KCD * KCD + 1; i += 128) kst[i] = g_kstart[i];
    __syncthreads();   // only barrier: kst visibility

    const int qi = sorted[blockIdx.x * QPW + warp];

    const float qx = cq[3 * qi + 0];
    const float qy = cq[3 * qi + 1];
    const float qz = cq[3 * qi + 2];

    int qcx = (int)(qx * KINV); qcx = qcx < 0 ? 0 : (qcx > KCD - 1 ? KCD - 1 : qcx);
    int qcy = (int)(qy * KINV); qcy = qcy < 0 ? 0 : (qcy > KCD - 1 ? KCD - 1 : qcy);
    int qcz = (int)(qz * KINV); qcz = qcz < 0 ? 0 : (qcz > KCD - 1 ? KCD - 1 : qcz);

    // Phase 1: warp-private candidate scan over <=27 cells
    int c = 0;
    int* mylist = list_s[warp];
    for (int dcx = -1; dcx <= 1; dcx++) {
        int cx = qcx + dcx;
        if (cx < 0 || cx >= KCD) continue;
        for (int dcy = -1; dcy <= 1; dcy++) {
            int cy = qcy + dcy;
            if (cy < 0 || cy >= KCD) continue;
            for (int dcz = -1; dcz <= 1; dcz++) {
                int cz = qcz + dcz;
                if (cz < 0 || cz >= KCD) continue;
                int cell = (cx * KCD + cy) * KCD + cz;
                int s = kst[cell], e = kst[cell + 1];
                for (int bse = s; bse < e; bse += 32) {
                    int j = bse + lane;
                    bool pass = false;
                    if (j < e) {
                        float dx = qx - g_ck2[3 * j + 0];
                        float dy = qy - g_ck2[3 * j + 1];
                        float dz = qz - g_ck2[3 * j + 2];
                        pass = (dx * dx + dy * dy + dz * dz) <= RADIUS2;
                    }
                    unsigned mk = __ballot_sync(0xffffffffu, pass);
                    if (pass) {
                        int pos = c + __popc(mk & ((1u << lane) - 1u));
                        if (pos < MAXN) mylist[pos] = j;
                    }
                    c += __popc(mk);
                }
            }
        }
    }
    const int n = (c < MAXN) ? c : MAXN;

    // Phase 2: all heads in one pass. q slice: 8 floats for this lane.
    const int d0 = lane * 8;
    const float4 q0 = *(const float4*)(g_q + (size_t)qi * 256 + d0);
    const float4 q1 = *(const float4*)(g_q + (size_t)qi * 256 + d0 + 4);
    const float* kb = g_k + d0;
    const float* vb = g_v + d0;

    float l = 0.0f;
    float4 a0 = make_float4(0.f, 0.f, 0.f, 0.f);
    float4 a1 = make_float4(0.f, 0.f, 0.f, 0.f);

    #pragma unroll 2
    for (int i = 0; i < n; i++) {
        const int j = mylist[i];
        const float4 k0 = *(const float4*)(kb + (size_t)j * 256);
        const float4 k1 = *(const float4*)(kb + (size_t)j * 256 + 4);

        float p = q0.x * k0.x;
        p = fmaf(q0.y, k0.y, p);
        p = fmaf(q0.z, k0.z, p);
        p = fmaf(q0.w, k0.w, p);
        p = fmaf(q1.x, k1.x, p);
        p = fmaf(q1.y, k1.y, p);
        p = fmaf(q1.z, k1.z, p);
        p = fmaf(q1.w, k1.w, p);
        // reduce within 4-lane head group
        p += __shfl_xor_sync(0xffffffffu, p, 1);
        p += __shfl_xor_sync(0xffffffffu, p, 2);

        float e = __expf(p * 0.17677669529663687f);   // 1/sqrt(32)
        l += e;                                        // identical across group

        const float4 v0 = *(const float4*)(vb + (size_t)j * 256);
        const float4 v1 = *(const float4*)(vb + (size_t)j * 256 + 4);
        a0.x = fmaf(e, v0.x, a0.x);
        a0.y = fmaf(e, v0.y, a0.y);
        a0.z = fmaf(e, v0.z, a0.z);
        a0.w = fmaf(e, v0.w, a0.w);
        a1.x = fmaf(e, v1.x, a1.x);
        a1.y = fmaf(e, v1.y, a1.y);
        a1.z = fmaf(e, v1.z, a1.z);
        a1.w = fmaf(e, v1.w, a1.w);
    }

    const float inv = 1.0f / l;
    float* op = out + (size_t)qi * 256 + d0;
    *(float4*)(op)     = make_float4(a0.x * inv, a0.y * inv, a0.z * inv, a0.w * inv);
    *(float4*)(op + 4) = make_float4(a1.x * inv, a1.y * inv, a1.z * inv, a1.w * inv);
}

// ---------------------------------------------------------------------------
extern "C" void kernel_launch(void* const* d_in, const int* in_sizes, int n_in,
                              void* d_out, int out_size)
{
    const float* cur_f  = (const float*)d_in[0];
    const float* hist_f = (const float*)d_in[1];
    const float* cur_c  = (const float*)d_in[2];
    const float* hist_c = (const float*)d_in[3];
    const float* Wq = (const float*)d_in[4];
    const float* bq = (const float*)d_in[5];
    const float* Wk = (const float*)d_in[6];
    const float* bk = (const float*)d_in[7];
    const float* Wv = (const float*)d_in[8];
    const float* bv = (const float*)d_in[9];
    const float* Wo = (const float*)d_in[10];
    const float* bo = (const float*)d_in[11];
    float* out = (float*)d_out;

    float *pq, *pk, *pv, *patt;
    int *psorted, *pkidx;
    cudaGetSymbolAddress((void**)&pq,   g_q);
    cudaGetSymbolAddress((void**)&pk,   g_k);
    cudaGetSymbolAddress((void**)&pv,   g_v);
    cudaGetSymbolAddress((void**)&patt, g_att);
    cudaGetSymbolAddress((void**)&psorted, g_sorted);
    cudaGetSymbolAddress((void**)&pkidx, g_kidx);

    sort_kernel<<<1, 512>>>(cur_c);
    sort_k_kernel<<<1, 512>>>(hist_c);

    dim3 gqkv(NQ / 128, FDIM / 64, 3);
    gemm_qkv_tc<<<gqkv, 256>>>(cur_f, hist_f,
                               Wq, bq, pq,
                               Wk, bk, pk,
                               Wv, bv, pv,
                               pkidx);

    attn_kernel<<<NQ / QPW, 128>>>(cur_c, psorted, patt);

    dim3 go(NQ / 64, FDIM / 64);
    gemm_o_tc<<<go, 256>>>(patt, Wo, bo, out);
}